// round 14
// baseline (speedup 1.0000x reference)
#include <cuda_runtime.h>
#include <math.h>
#include <stdint.h>

#define BB  128   // batch
#define TT  256   // time steps
#define TD  256   // feature dim D
#define NS  32    // stack depth

// ---------------------------------------------------------------------------
// Device scratch (no allocations allowed)
// ---------------------------------------------------------------------------
__device__ float      g_scratch[BB * TT];          // latch gates g[b][t]
__device__ float      pop_scratch[BB * TT];        // pop[b][t]
__device__ ulonglong2 coef2_buf[BB * TT * NS * 2]; // {a,a,e,e},{c,c,w,w}

__device__ __forceinline__ float ex2f(float v) {
    float r; asm("ex2.approx.f32 %0, %1;" : "=f"(r) : "f"(v)); return r;
}
__device__ __forceinline__ void cp16(uint32_t saddr, const void* gaddr) {
    asm volatile("cp.async.cg.shared.global [%0], [%1], 16;"
                 :: "r"(saddr), "l"(gaddr));
}
#define CP_COMMIT() asm volatile("cp.async.commit_group;")
#define CP_WAIT1()  asm volatile("cp.async.wait_group 1;")

// f32x2 packed math (Blackwell, PTX-only)
#define FMA2(d, a, b, c) \
    asm("fma.rn.f32x2 %0, %1, %2, %3;" : "=l"(d) : "l"(a), "l"(b), "l"(c))
#define ADD2(d, a, b) \
    asm("add.rn.f32x2 %0, %1, %2;" : "=l"(d) : "l"(a), "l"(b))
#define PACK2(d, lo, hi) \
    asm("mov.b64 %0, {%1, %2};" : "=l"(d) : "f"(lo), "f"(hi))
#define UNPACK2(lo, hi, s) \
    asm("mov.b64 {%0, %1}, %2;" : "=f"(lo), "=f"(hi) : "l"(s))

// ---------------------------------------------------------------------------
// K1: g[b][t] = elu(cos_sim(latch_enable, x[b,t,:])). One warp per (b,t).
// ---------------------------------------------------------------------------
__global__ void __launch_bounds__(256) precompute_g_kernel(
    const float* __restrict__ x,
    const float* __restrict__ le)
{
    const int warp = threadIdx.x >> 5;
    const int lane = threadIdx.x & 31;
    const int bt   = blockIdx.x * 8 + warp;
    const float* xp = x + (size_t)bt * TD;

    float dot = 0.f, nx = 0.f, nl = 0.f;
#pragma unroll
    for (int k = 0; k < 8; k++) {
        float xv = xp[lane + k * 32];
        float lv = le[lane + k * 32];
        dot = fmaf(lv, xv, dot);
        nx  = fmaf(xv, xv, nx);
        nl  = fmaf(lv, lv, nl);
    }
#pragma unroll
    for (int o = 16; o; o >>= 1) {
        dot += __shfl_xor_sync(0xffffffffu, dot, o);
        nx  += __shfl_xor_sync(0xffffffffu, nx,  o);
        nl  += __shfl_xor_sync(0xffffffffu, nl,  o);
    }
    if (lane == 0) {
        float an = fmaxf(sqrtf(nl), 1e-8f);
        float bn = fmaxf(sqrtf(nx), 1e-8f);
        float c  = dot / (an * bn);
        g_scratch[bt] = (c > 0.f) ? c : expm1f(c);
    }
}

// ---------------------------------------------------------------------------
// K2ab: fused latch scan + pop reduction. One CTA per batch; thread d carries
// latch[d]. Per step: warp butterfly into a per-warp smem row (no in-loop
// barrier). One __syncthreads, then thread t finishes pop[b][t].
// ---------------------------------------------------------------------------
__global__ void __launch_bounds__(256) latch_pop_kernel(
    const float* __restrict__ x,
    const float* __restrict__ should_pop,
    const float* __restrict__ latch_init)
{
    __shared__ float2 part[8][TT];    // 16 KB
    __shared__ float  spn[8];

    const int b    = blockIdx.x;
    const int d    = threadIdx.x;
    const int warp = d >> 5;
    const int lane = d & 31;

    const float sp = should_pop[d];
    float lat      = latch_init[b * TD + d];

    {
        float r = sp * sp;
#pragma unroll
        for (int o = 16; o; o >>= 1) r += __shfl_xor_sync(0xffffffffu, r, o);
        if (lane == 0) spn[warp] = r;
    }
    __syncthreads();
    float sp2 = 0.f;
#pragma unroll
    for (int w = 0; w < 8; w++) sp2 += spn[w];
    const float inv_an = 1.0f / fmaxf(sqrtf(sp2), 1e-8f);

    const float* xb = x + (size_t)b * TT * TD + d;
    const float* gb = g_scratch + b * TT;

#pragma unroll 4
    for (int t = 0; t < TT; t++) {
        float q0 = sp * lat, q1 = lat * lat;
#pragma unroll
        for (int o = 16; o; o >>= 1) {
            q0 += __shfl_xor_sync(0xffffffffu, q0, o);
            q1 += __shfl_xor_sync(0xffffffffu, q1, o);
        }
        if (lane == 0) part[warp][t] = make_float2(q0, q1);

        float xv = __ldg(xb + (size_t)t * TD);
        float gg = __ldg(gb + t);
        lat = fmaf(gg, xv - lat, lat);
    }
    __syncthreads();

    {
        const int t = d;
        float dot = 0.f, nl = 0.f;
#pragma unroll
        for (int w = 0; w < 8; w++) {
            float2 p = part[w][t];
            dot += p.x; nl += p.y;
        }
        float bn   = fmaxf(sqrtf(nl), 1e-8f);
        float cosv = dot * inv_an / bn;
        pop_scratch[b * TT + t] = (cosv > 0.f) ? cosv : expm1f(cosv);
    }
}

// ---------------------------------------------------------------------------
// K2c: pointer scan. One warp per batch. Sigma butterfly interleaved with the
// roll/lg2 chain; ex2.approx sharpen; coef store deferred one step. Coefs
// written pre-duplicated for K3's f32x2 path.
// ---------------------------------------------------------------------------
__global__ void __launch_bounds__(32) pointer_scan_kernel(
    const float* __restrict__ sharpen_ptr)
{
    const int b    = blockIdx.x;
    const int lane = threadIdx.x;
    const unsigned FULL = 0xffffffffu;

    const float s5 = sharpen_ptr[0];

    float Q = (lane == 0) ? 1.0f : 1e-6f;   // raw initial pointer

    const float* pb = pop_scratch + b * TT;
    float4*      cb = (float4*)(coef2_buf + (size_t)b * TT * NS * 2);

    float popPrev = 0.f, aPrev = 0.f, ePrev = 0.f, cPrev = 0.f;

#pragma unroll 4
    for (int t = 0; t < TT; t++) {
        const float pop  = __ldg(pb + t);
        const float push = 1.0f - pop;

        float sig = Q;
        float Qp = __shfl_sync(FULL, Q, (lane + 31) & 31);  // p_push source
        sig += __shfl_xor_sync(FULL, sig, 1);
        float Qm = __shfl_sync(FULL, Q, (lane + 1) & 31);   // p_pop source
        sig += __shfl_xor_sync(FULL, sig, 2);
        float np = fmaf(push, Qp, pop * Qm);                // unnormalized new ptr
        sig += __shfl_xor_sync(FULL, sig, 4);
        float lnp = __log2f(np);
        sig += __shfl_xor_sync(FULL, sig, 8);
        sig += __shfl_xor_sync(FULL, sig, 16);

        float invs = 1.0f / sig;
        float lgs  = __log2f(sig);

        if (t > 0) {
            float w = popPrev * Q * invs;
            cb[((t - 1) * NS + lane) * 2]     = make_float4(aPrev, aPrev, ePrev, ePrev);
            cb[((t - 1) * NS + lane) * 2 + 1] = make_float4(cPrev, cPrev, w, w);
        }

        float e = push * (Qp * invs);
        float f = pop  * (Q  * invs);
        float a = 1.0f - e - f;
        float c = 1e-6f * f;

        float Qn = (np > 0.f) ? ex2f(s5 * (lnp - lgs)) : 0.f;

        Q = Qn;
        popPrev = pop; aPrev = a; ePrev = e; cPrev = c;
    }

    {
        float sig = Q;
#pragma unroll
        for (int o = 16; o; o >>= 1) sig += __shfl_xor_sync(FULL, sig, o);
        float invs = 1.0f / fmaxf(sig, 1e-8f);
        float w = popPrev * Q * invs;
        cb[((TT - 1) * NS + lane) * 2]     = make_float4(aPrev, aPrev, ePrev, ePrev);
        cb[((TT - 1) * NS + lane) * 2 + 1] = make_float4(cPrev, cPrev, w, w);
    }
}

// ---------------------------------------------------------------------------
// K3: stack recurrence, f32x2, 256 threads (8 warps). Thread tid = 2c + h:
// column-pair c (cols 2c,2c+1), slot half h (16 slots). Readout combined
// across the lane pair with one 64-bit shfl + packed add; thread writes
// scalar column tid. Coefs staged in 8-step chunks, double-buffered via
// cp.async: TWO barriers per 8 steps instead of one per step.
// ---------------------------------------------------------------------------
__global__ void __launch_bounds__(256) stack_kernel(
    const float* __restrict__ x,
    float* __restrict__ out)
{
    __shared__ ulonglong2 cbuf[2][8 * 64];   // 16 KB: 2 chunks x 8 steps x 64

    const int tid = threadIdx.x;
    const int b   = blockIdx.x;
    const int c   = tid >> 1;          // column pair 0..127
    const int h   = tid & 1;           // slot half

    const ulonglong2* cb  = coef2_buf + (size_t)b * TT * NS * 2;
    const float2*     xb2 = (const float2*)(x + (size_t)b * TT * TD) + c;
    float*            ob  = out + (size_t)b * TT * TD + tid;

    unsigned long long st2[16];
    {
        unsigned long long init;
        PACK2(init, 1e-6f, 1e-6f);
#pragma unroll
        for (int n = 0; n < 16; n++) st2[n] = init;
    }

    // prologue: chunks 0 and 1 in flight (512 entries each; 2 per thread)
    {
        uint32_t s0 = (uint32_t)__cvta_generic_to_shared(&cbuf[0][0]);
        cp16(s0 + tid * 16,           &cb[tid]);        // chunk 0
        cp16(s0 + (tid + 256) * 16,   &cb[tid + 256]);
        CP_COMMIT();
        cp16(s0 + 8192 + tid * 16,         &cb[512 + tid]);   // chunk 1
        cp16(s0 + 8192 + (tid + 256) * 16, &cb[512 + tid + 256]);
        CP_COMMIT();
        CP_WAIT1();                    // chunk 0 complete
    }
    __syncthreads();

    for (int k = 0; k < TT / 8; k++) {
        const ulonglong2* chunk = cbuf[k & 1];

#pragma unroll
        for (int s = 0; s < 8; s++) {
            const int t = k * 8 + s;
            float2 xv = __ldg(xb2 + (size_t)t * (TD / 2));

            unsigned long long in2, s2a, s2b;
            PACK2(in2, xv.x, xv.y);
            PACK2(s2a, 0.0f, 0.0f);
            PACK2(s2b, 0.0f, 0.0f);

            const ulonglong2* cf = chunk + s * 64 + h * 32;
#pragma unroll
            for (int n = 0; n < 16; n++) {
                ulonglong2 A = cf[2 * n];        // {a,a | e,e}
                ulonglong2 B = cf[2 * n + 1];    // {c,c | w,w}
                unsigned long long z2, v2;
                FMA2(z2, A.y, in2, B.x);         // e*in + c
                FMA2(v2, A.x, st2[n], z2);       // a*st + z
                st2[n] = v2;
                if (n & 1) { FMA2(s2b, v2, B.y, s2b); }
                else       { FMA2(s2a, v2, B.y, s2a); }
            }
            unsigned long long s2, sc;
            ADD2(s2, s2a, s2b);
            // combine the two slot-halves (partner = lane^1)
            unsigned long long so = __shfl_xor_sync(0xffffffffu, s2, 1);
            ADD2(sc, s2, so);
            float lo, hi;
            UNPACK2(lo, hi, sc);
            ob[(size_t)t * TD] = h ? hi : lo;
        }

        __syncthreads();               // everyone done reading slot k&1
        if (k + 2 < TT / 8) {
            uint32_t sa = (uint32_t)__cvta_generic_to_shared(&cbuf[k & 1][0]);
            cp16(sa + tid * 16,         &cb[(size_t)(k + 2) * 512 + tid]);
            cp16(sa + (tid + 256) * 16, &cb[(size_t)(k + 2) * 512 + tid + 256]);
        }
        CP_COMMIT();                   // uniform group count
        CP_WAIT1();                    // chunk k+1 complete (this thread)
        __syncthreads();               // ... visible to all threads
    }
}

// ---------------------------------------------------------------------------
// metadata order: x[B*T*D], should_pop[D], sharpen_pointer[1],
//                 latch_enable[D], latch_init[B*D]  -> out[B*T*D] float32
// ---------------------------------------------------------------------------
extern "C" void kernel_launch(void* const* d_in, const int* in_sizes, int n_in,
                              void* d_out, int out_size)
{
    const float* x   = (const float*)d_in[0];
    const float* sp  = (const float*)d_in[1];
    const float* shp = (const float*)d_in[2];
    const float* le  = (const float*)d_in[3];
    const float* li  = (const float*)d_in[4];
    float* out = (float*)d_out;

    precompute_g_kernel<<<(BB * TT) / 8, 256>>>(x, le);
    latch_pop_kernel<<<BB, 256>>>(x, sp, li);
    pointer_scan_kernel<<<BB, 32>>>(shp);
    stack_kernel<<<BB, 256>>>(x, out);
}

// round 15
// speedup vs baseline: 1.3913x; 1.3913x over previous
#include <cuda_runtime.h>
#include <math.h>
#include <stdint.h>

#define BB  128   // batch
#define TT  256   // time steps
#define TD  256   // feature dim D
#define NS  32    // stack depth

// ---------------------------------------------------------------------------
// Device scratch (no allocations allowed)
// ---------------------------------------------------------------------------
__device__ float  g_scratch[BB * TT];        // latch gates g[b][t]
__device__ float  pop_scratch[BB * TT];      // pop[b][t]
__device__ float4 coef_buf[BB * TT * NS];    // {a, e, c, w} per (b,t,slot)

__device__ __forceinline__ float ex2f(float v) {
    float r; asm("ex2.approx.f32 %0, %1;" : "=f"(r) : "f"(v)); return r;
}
__device__ __forceinline__ void cp16(uint32_t saddr, const void* gaddr) {
    asm volatile("cp.async.cg.shared.global [%0], [%1], 16;"
                 :: "r"(saddr), "l"(gaddr));
}
#define CP_COMMIT() asm volatile("cp.async.commit_group;")
#define CP_WAIT1()  asm volatile("cp.async.wait_group 1;")

// ---------------------------------------------------------------------------
// K1: g[b][t] = elu(cos_sim(latch_enable, x[b,t,:])). One warp per (b,t).
// ---------------------------------------------------------------------------
__global__ void __launch_bounds__(256) precompute_g_kernel(
    const float* __restrict__ x,
    const float* __restrict__ le)
{
    const int warp = threadIdx.x >> 5;
    const int lane = threadIdx.x & 31;
    const int bt   = blockIdx.x * 8 + warp;
    const float* xp = x + (size_t)bt * TD;

    float dot = 0.f, nx = 0.f, nl = 0.f;
#pragma unroll
    for (int k = 0; k < 8; k++) {
        float xv = xp[lane + k * 32];
        float lv = le[lane + k * 32];
        dot = fmaf(lv, xv, dot);
        nx  = fmaf(xv, xv, nx);
        nl  = fmaf(lv, lv, nl);
    }
#pragma unroll
    for (int o = 16; o; o >>= 1) {
        dot += __shfl_xor_sync(0xffffffffu, dot, o);
        nx  += __shfl_xor_sync(0xffffffffu, nx,  o);
        nl  += __shfl_xor_sync(0xffffffffu, nl,  o);
    }
    if (lane == 0) {
        float an = fmaxf(sqrtf(nl), 1e-8f);
        float bn = fmaxf(sqrtf(nx), 1e-8f);
        float c  = dot / (an * bn);
        g_scratch[bt] = (c > 0.f) ? c : expm1f(c);
    }
}

// ---------------------------------------------------------------------------
// K2ab: fused latch scan + pop reduction. One CTA per batch; thread d carries
// latch[d]. Per step: warp butterfly into a per-warp smem row (no in-loop
// barrier). One __syncthreads, then thread t finishes pop[b][t].
// ---------------------------------------------------------------------------
__global__ void __launch_bounds__(256) latch_pop_kernel(
    const float* __restrict__ x,
    const float* __restrict__ should_pop,
    const float* __restrict__ latch_init)
{
    __shared__ float2 part[8][TT];    // 16 KB
    __shared__ float  spn[8];

    const int b    = blockIdx.x;
    const int d    = threadIdx.x;
    const int warp = d >> 5;
    const int lane = d & 31;

    const float sp = should_pop[d];
    float lat      = latch_init[b * TD + d];

    {
        float r = sp * sp;
#pragma unroll
        for (int o = 16; o; o >>= 1) r += __shfl_xor_sync(0xffffffffu, r, o);
        if (lane == 0) spn[warp] = r;
    }
    __syncthreads();
    float sp2 = 0.f;
#pragma unroll
    for (int w = 0; w < 8; w++) sp2 += spn[w];
    const float inv_an = 1.0f / fmaxf(sqrtf(sp2), 1e-8f);

    const float* xb = x + (size_t)b * TT * TD + d;
    const float* gb = g_scratch + b * TT;

#pragma unroll 4
    for (int t = 0; t < TT; t++) {
        float q0 = sp * lat, q1 = lat * lat;
#pragma unroll
        for (int o = 16; o; o >>= 1) {
            q0 += __shfl_xor_sync(0xffffffffu, q0, o);
            q1 += __shfl_xor_sync(0xffffffffu, q1, o);
        }
        if (lane == 0) part[warp][t] = make_float2(q0, q1);

        float xv = __ldg(xb + (size_t)t * TD);
        float gg = __ldg(gb + t);
        lat = fmaf(gg, xv - lat, lat);
    }
    __syncthreads();

    {
        const int t = d;
        float dot = 0.f, nl = 0.f;
#pragma unroll
        for (int w = 0; w < 8; w++) {
            float2 p = part[w][t];
            dot += p.x; nl += p.y;
        }
        float bn   = fmaxf(sqrtf(nl), 1e-8f);
        float cosv = dot * inv_an / bn;
        pop_scratch[b * TT + t] = (cosv > 0.f) ? cosv : expm1f(cosv);
    }
}

// ---------------------------------------------------------------------------
// K2c: pointer scan. One warp per batch. Sigma butterfly interleaved with the
// roll/lg2 chain; ex2.approx sharpen; coef store deferred one step.
// ---------------------------------------------------------------------------
__global__ void __launch_bounds__(32) pointer_scan_kernel(
    const float* __restrict__ sharpen_ptr)
{
    const int b    = blockIdx.x;
    const int lane = threadIdx.x;
    const unsigned FULL = 0xffffffffu;

    const float s5 = sharpen_ptr[0];

    float Q = (lane == 0) ? 1.0f : 1e-6f;   // raw initial pointer

    const float* pb = pop_scratch + b * TT;
    float4*      cb = coef_buf + (size_t)b * TT * NS;

    float popPrev = 0.f, aPrev = 0.f, ePrev = 0.f, cPrev = 0.f;

#pragma unroll 4
    for (int t = 0; t < TT; t++) {
        const float pop  = __ldg(pb + t);
        const float push = 1.0f - pop;

        float sig = Q;
        float Qp = __shfl_sync(FULL, Q, (lane + 31) & 31);  // p_push source
        sig += __shfl_xor_sync(FULL, sig, 1);
        float Qm = __shfl_sync(FULL, Q, (lane + 1) & 31);   // p_pop source
        sig += __shfl_xor_sync(FULL, sig, 2);
        float np = fmaf(push, Qp, pop * Qm);                // unnormalized new ptr
        sig += __shfl_xor_sync(FULL, sig, 4);
        float lnp = __log2f(np);
        sig += __shfl_xor_sync(FULL, sig, 8);
        sig += __shfl_xor_sync(FULL, sig, 16);

        float invs = 1.0f / sig;
        float lgs  = __log2f(sig);

        if (t > 0) {
            float w = popPrev * Q * invs;
            cb[(t - 1) * NS + lane] = make_float4(aPrev, ePrev, cPrev, w);
        }

        float e = push * (Qp * invs);
        float f = pop  * (Q  * invs);
        float a = 1.0f - e - f;
        float c = 1e-6f * f;

        float Qn = (np > 0.f) ? ex2f(s5 * (lnp - lgs)) : 0.f;

        Q = Qn;
        popPrev = pop; aPrev = a; ePrev = e; cPrev = c;
    }

    {
        float sig = Q;
#pragma unroll
        for (int o = 16; o; o >>= 1) sig += __shfl_xor_sync(FULL, sig, o);
        float invs = 1.0f / fmaxf(sig, 1e-8f);
        float w = popPrev * Q * invs;
        cb[(TT - 1) * NS + lane] = make_float4(aPrev, ePrev, cPrev, w);
    }
}

// ---------------------------------------------------------------------------
// K3: stack recurrence, scalar. 256 threads (8 warps), thread = column d,
// st[32] in registers. Coefs staged in 8-step chunks (8 KB, double-buffered,
// one cp.async per thread per chunk); x prefetched per chunk. All smem coef
// reads are warp-uniform broadcasts (conflict-free). 2 barriers per 8 steps.
// ---------------------------------------------------------------------------
__global__ void __launch_bounds__(256) stack_kernel(
    const float* __restrict__ x,
    float* __restrict__ out)
{
    __shared__ float4 cbuf[2][8][NS];   // 8 KB: 2 chunks x 8 steps x 32 slots

    const int tid = threadIdx.x;
    const int b   = blockIdx.x;

    const float4* cb = coef_buf + (size_t)b * TT * NS;
    const float*  xb = x   + (size_t)b * TT * TD + tid;
    float*        ob = out + (size_t)b * TT * TD + tid;

    float st[NS];
#pragma unroll
    for (int n = 0; n < NS; n++) st[n] = 1e-6f;

    // prologue: chunks 0 and 1 in flight (256 float4 each; 1 per thread)
    {
        uint32_t s0 = (uint32_t)__cvta_generic_to_shared(&cbuf[0][0][0]);
        cp16(s0 + tid * 16,        &cb[tid]);         CP_COMMIT();
        cp16(s0 + 4096 + tid * 16, &cb[256 + tid]);   CP_COMMIT();
        CP_WAIT1();                    // chunk 0 complete
    }
    __syncthreads();

    for (int k = 0; k < TT / 8; k++) {
        // prefetch this chunk's 8 x values (independent loads, MLP=8)
        float xv[8];
#pragma unroll
        for (int s = 0; s < 8; s++)
            xv[s] = __ldg(xb + (size_t)(k * 8 + s) * TD);

#pragma unroll
        for (int s = 0; s < 8; s++) {
            const int t = k * 8 + s;
            const float4* cf = cbuf[k & 1][s];
            float ss = 0.f;
#pragma unroll
            for (int n = 0; n < NS; n++) {
                float4 kk = cf[n];
                float v = fmaf(kk.x, st[n], fmaf(kk.y, xv[s], kk.z));
                st[n] = v;
                ss = fmaf(v, kk.w, ss);
            }
            ob[(size_t)t * TD] = ss;
        }

        __syncthreads();               // all warps done reading slot k&1
        if (k + 2 < TT / 8) {
            uint32_t sa = (uint32_t)__cvta_generic_to_shared(&cbuf[k & 1][0][0]);
            cp16(sa + tid * 16, &cb[(size_t)(k + 2) * 256 + tid]);
        }
        CP_COMMIT();                   // uniform group count
        CP_WAIT1();                    // chunk k+1 complete (this thread)
        __syncthreads();               // ... and visible to all
    }
}

// ---------------------------------------------------------------------------
// metadata order: x[B*T*D], should_pop[D], sharpen_pointer[1],
//                 latch_enable[D], latch_init[B*D]  -> out[B*T*D] float32
// ---------------------------------------------------------------------------
extern "C" void kernel_launch(void* const* d_in, const int* in_sizes, int n_in,
                              void* d_out, int out_size)
{
    const float* x   = (const float*)d_in[0];
    const float* sp  = (const float*)d_in[1];
    const float* shp = (const float*)d_in[2];
    const float* le  = (const float*)d_in[3];
    const float* li  = (const float*)d_in[4];
    float* out = (float*)d_out;

    precompute_g_kernel<<<(BB * TT) / 8, 256>>>(x, le);
    latch_pop_kernel<<<BB, 256>>>(x, sp, li);
    pointer_scan_kernel<<<BB, 32>>>(shp);
    stack_kernel<<<BB, 256>>>(x, out);
}

// round 16
// speedup vs baseline: 1.5046x; 1.0815x over previous
#include <cuda_runtime.h>
#include <math.h>
#include <stdint.h>

#define BB  128   // batch
#define TT  256   // time steps
#define TD  256   // feature dim D
#define NS  32    // stack depth

// ---------------------------------------------------------------------------
// Device scratch (no allocations allowed)
// ---------------------------------------------------------------------------
__device__ float  g_scratch[BB * TT];        // latch gates g[b][t]
__device__ float  pop_scratch[BB * TT];      // pop[b][t]
__device__ float4 coef_buf[BB * TT * NS];    // {a, e, c, w} per (b,t,slot)

__device__ __forceinline__ float ex2f(float v) {
    float r; asm("ex2.approx.f32 %0, %1;" : "=f"(r) : "f"(v)); return r;
}
__device__ __forceinline__ float rcpf(float v) {
    float r; asm("rcp.approx.f32 %0, %1;" : "=f"(r) : "f"(v)); return r;
}
__device__ __forceinline__ void cp16(uint32_t saddr, const void* gaddr) {
    asm volatile("cp.async.cg.shared.global [%0], [%1], 16;"
                 :: "r"(saddr), "l"(gaddr));
}
#define CP_COMMIT() asm volatile("cp.async.commit_group;")
#define CP_WAIT1()  asm volatile("cp.async.wait_group 1;")

// ---------------------------------------------------------------------------
// K1: g[b][t] = elu(cos_sim(latch_enable, x[b,t,:])). One warp per (b,t).
// ---------------------------------------------------------------------------
__global__ void __launch_bounds__(256) precompute_g_kernel(
    const float* __restrict__ x,
    const float* __restrict__ le)
{
    const int warp = threadIdx.x >> 5;
    const int lane = threadIdx.x & 31;
    const int bt   = blockIdx.x * 8 + warp;
    const float* xp = x + (size_t)bt * TD;

    float dot = 0.f, nx = 0.f, nl = 0.f;
#pragma unroll
    for (int k = 0; k < 8; k++) {
        float xv = xp[lane + k * 32];
        float lv = le[lane + k * 32];
        dot = fmaf(lv, xv, dot);
        nx  = fmaf(xv, xv, nx);
        nl  = fmaf(lv, lv, nl);
    }
#pragma unroll
    for (int o = 16; o; o >>= 1) {
        dot += __shfl_xor_sync(0xffffffffu, dot, o);
        nx  += __shfl_xor_sync(0xffffffffu, nx,  o);
        nl  += __shfl_xor_sync(0xffffffffu, nl,  o);
    }
    if (lane == 0) {
        float an = fmaxf(sqrtf(nl), 1e-8f);
        float bn = fmaxf(sqrtf(nx), 1e-8f);
        float c  = dot / (an * bn);
        g_scratch[bt] = (c > 0.f) ? c : expm1f(c);
    }
}

// ---------------------------------------------------------------------------
// K2ab: fused latch scan + pop reduction. One CTA per batch; thread d carries
// latch[d]. Per step: warp butterfly into a per-warp smem row (no in-loop
// barrier). One __syncthreads, then thread t finishes pop[b][t].
// ---------------------------------------------------------------------------
__global__ void __launch_bounds__(256) latch_pop_kernel(
    const float* __restrict__ x,
    const float* __restrict__ should_pop,
    const float* __restrict__ latch_init)
{
    __shared__ float2 part[8][TT];    // 16 KB
    __shared__ float  spn[8];

    const int b    = blockIdx.x;
    const int d    = threadIdx.x;
    const int warp = d >> 5;
    const int lane = d & 31;

    const float sp = should_pop[d];
    float lat      = latch_init[b * TD + d];

    {
        float r = sp * sp;
#pragma unroll
        for (int o = 16; o; o >>= 1) r += __shfl_xor_sync(0xffffffffu, r, o);
        if (lane == 0) spn[warp] = r;
    }
    __syncthreads();
    float sp2 = 0.f;
#pragma unroll
    for (int w = 0; w < 8; w++) sp2 += spn[w];
    const float inv_an = 1.0f / fmaxf(sqrtf(sp2), 1e-8f);

    const float* xb = x + (size_t)b * TT * TD + d;
    const float* gb = g_scratch + b * TT;

#pragma unroll 4
    for (int t = 0; t < TT; t++) {
        float q0 = sp * lat, q1 = lat * lat;
#pragma unroll
        for (int o = 16; o; o >>= 1) {
            q0 += __shfl_xor_sync(0xffffffffu, q0, o);
            q1 += __shfl_xor_sync(0xffffffffu, q1, o);
        }
        if (lane == 0) part[warp][t] = make_float2(q0, q1);

        float xv = __ldg(xb + (size_t)t * TD);
        float gg = __ldg(gb + t);
        lat = fmaf(gg, xv - lat, lat);
    }
    __syncthreads();

    {
        const int t = d;
        float dot = 0.f, nl = 0.f;
#pragma unroll
        for (int w = 0; w < 8; w++) {
            float2 p = part[w][t];
            dot += p.x; nl += p.y;
        }
        float bn   = fmaxf(sqrtf(nl), 1e-8f);
        float cosv = dot * inv_an / bn;
        pop_scratch[b * TT + t] = (cosv > 0.f) ? cosv : expm1f(cosv);
    }
}

// ---------------------------------------------------------------------------
// K2c: pointer scan. One warp per batch. Sigma butterfly interleaved with the
// roll/lg2 chain; ex2.approx sharpen; rcp.approx for the (off-chain) 1/sigma;
// coef store deferred one step.
// ---------------------------------------------------------------------------
__global__ void __launch_bounds__(32) pointer_scan_kernel(
    const float* __restrict__ sharpen_ptr)
{
    const int b    = blockIdx.x;
    const int lane = threadIdx.x;
    const unsigned FULL = 0xffffffffu;

    const float s5 = sharpen_ptr[0];

    float Q = (lane == 0) ? 1.0f : 1e-6f;   // raw initial pointer

    const float* pb = pop_scratch + b * TT;
    float4*      cb = coef_buf + (size_t)b * TT * NS;

    float popPrev = 0.f, aPrev = 0.f, ePrev = 0.f, cPrev = 0.f;

#pragma unroll 4
    for (int t = 0; t < TT; t++) {
        const float pop  = __ldg(pb + t);
        const float push = 1.0f - pop;

        float sig = Q;
        float Qp = __shfl_sync(FULL, Q, (lane + 31) & 31);  // p_push source
        sig += __shfl_xor_sync(FULL, sig, 1);
        float Qm = __shfl_sync(FULL, Q, (lane + 1) & 31);   // p_pop source
        sig += __shfl_xor_sync(FULL, sig, 2);
        float np = fmaf(push, Qp, pop * Qm);                // unnormalized new ptr
        sig += __shfl_xor_sync(FULL, sig, 4);
        float lnp = __log2f(np);
        sig += __shfl_xor_sync(FULL, sig, 8);
        sig += __shfl_xor_sync(FULL, sig, 16);

        float invs = rcpf(sig);          // off the Q-chain; 1-ulp approx
        float lgs  = __log2f(sig);

        if (t > 0) {
            float w = popPrev * Q * invs;
            cb[(t - 1) * NS + lane] = make_float4(aPrev, ePrev, cPrev, w);
        }

        float e = push * (Qp * invs);
        float f = pop  * (Q  * invs);
        float a = 1.0f - e - f;
        float c = 1e-6f * f;

        float Qn = (np > 0.f) ? ex2f(s5 * (lnp - lgs)) : 0.f;

        Q = Qn;
        popPrev = pop; aPrev = a; ePrev = e; cPrev = c;
    }

    {
        float sig = Q;
#pragma unroll
        for (int o = 16; o; o >>= 1) sig += __shfl_xor_sync(FULL, sig, o);
        float invs = rcpf(fmaxf(sig, 1e-8f));
        float w = popPrev * Q * invs;
        cb[(TT - 1) * NS + lane] = make_float4(aPrev, ePrev, cPrev, w);
    }
}

// ---------------------------------------------------------------------------
// K3: stack recurrence, scalar. 256 threads (8 warps), thread = column d,
// st[32] in registers. Coefs staged in 8-step chunks (8 KB, double-buffered);
// x prefetched per chunk. Readout uses FOUR parallel accumulators: the old
// single-accumulator version had a 128-cyc serial FMA chain per step that
// capped issue at ~24%.
// ---------------------------------------------------------------------------
__global__ void __launch_bounds__(256) stack_kernel(
    const float* __restrict__ x,
    float* __restrict__ out)
{
    __shared__ float4 cbuf[2][8][NS];   // 8 KB: 2 chunks x 8 steps x 32 slots

    const int tid = threadIdx.x;
    const int b   = blockIdx.x;

    const float4* cb = coef_buf + (size_t)b * TT * NS;
    const float*  xb = x   + (size_t)b * TT * TD + tid;
    float*        ob = out + (size_t)b * TT * TD + tid;

    float st[NS];
#pragma unroll
    for (int n = 0; n < NS; n++) st[n] = 1e-6f;

    // prologue: chunks 0 and 1 in flight (256 float4 each; 1 per thread)
    {
        uint32_t s0 = (uint32_t)__cvta_generic_to_shared(&cbuf[0][0][0]);
        cp16(s0 + tid * 16,        &cb[tid]);         CP_COMMIT();
        cp16(s0 + 4096 + tid * 16, &cb[256 + tid]);   CP_COMMIT();
        CP_WAIT1();                    // chunk 0 complete
    }
    __syncthreads();

    for (int k = 0; k < TT / 8; k++) {
        // prefetch this chunk's 8 x values (independent loads, MLP=8)
        float xv[8];
#pragma unroll
        for (int s = 0; s < 8; s++)
            xv[s] = __ldg(xb + (size_t)(k * 8 + s) * TD);

#pragma unroll
        for (int s = 0; s < 8; s++) {
            const int t = k * 8 + s;
            const float4* cf = cbuf[k & 1][s];
            float s0 = 0.f, s1 = 0.f, s2 = 0.f, s3 = 0.f;
#pragma unroll
            for (int n = 0; n < NS; n += 4) {
                float4 k0 = cf[n];
                float4 k1 = cf[n + 1];
                float4 k2 = cf[n + 2];
                float4 k3 = cf[n + 3];
                float v0 = fmaf(k0.x, st[n],     fmaf(k0.y, xv[s], k0.z));
                float v1 = fmaf(k1.x, st[n + 1], fmaf(k1.y, xv[s], k1.z));
                float v2 = fmaf(k2.x, st[n + 2], fmaf(k2.y, xv[s], k2.z));
                float v3 = fmaf(k3.x, st[n + 3], fmaf(k3.y, xv[s], k3.z));
                st[n]     = v0;
                st[n + 1] = v1;
                st[n + 2] = v2;
                st[n + 3] = v3;
                s0 = fmaf(v0, k0.w, s0);
                s1 = fmaf(v1, k1.w, s1);
                s2 = fmaf(v2, k2.w, s2);
                s3 = fmaf(v3, k3.w, s3);
            }
            ob[(size_t)t * TD] = (s0 + s1) + (s2 + s3);
        }

        __syncthreads();               // all warps done reading slot k&1
        if (k + 2 < TT / 8) {
            uint32_t sa = (uint32_t)__cvta_generic_to_shared(&cbuf[k & 1][0][0]);
            cp16(sa + tid * 16, &cb[(size_t)(k + 2) * 256 + tid]);
        }
        CP_COMMIT();                   // uniform group count
        CP_WAIT1();                    // chunk k+1 complete (this thread)
        __syncthreads();               // ... and visible to all
    }
}

// ---------------------------------------------------------------------------
// metadata order: x[B*T*D], should_pop[D], sharpen_pointer[1],
//                 latch_enable[D], latch_init[B*D]  -> out[B*T*D] float32
// ---------------------------------------------------------------------------
extern "C" void kernel_launch(void* const* d_in, const int* in_sizes, int n_in,
                              void* d_out, int out_size)
{
    const float* x   = (const float*)d_in[0];
    const float* sp  = (const float*)d_in[1];
    const float* shp = (const float*)d_in[2];
    const float* le  = (const float*)d_in[3];
    const float* li  = (const float*)d_in[4];
    float* out = (float*)d_out;

    precompute_g_kernel<<<(BB * TT) / 8, 256>>>(x, le);
    latch_pop_kernel<<<BB, 256>>>(x, sp, li);
    pointer_scan_kernel<<<BB, 32>>>(shp);
    stack_kernel<<<BB, 256>>>(x, out);
}

// round 17
// speedup vs baseline: 1.5337x; 1.0193x over previous
#include <cuda_runtime.h>
#include <math.h>
#include <stdint.h>

#define BB  128   // batch
#define TT  256   // time steps
#define TD  256   // feature dim D
#define NS  32    // stack depth

// ---------------------------------------------------------------------------
// Device scratch (no allocations allowed)
// ---------------------------------------------------------------------------
__device__ float  g_scratch[BB * TT];        // latch gates g[b][t]
__device__ float  pop_scratch[BB * TT];      // pop[b][t]
__device__ float4 coef_buf[BB * TT * NS];    // {a, e, c, w} per (b,t,slot)

__device__ __forceinline__ float ex2f(float v) {
    float r; asm("ex2.approx.f32 %0, %1;" : "=f"(r) : "f"(v)); return r;
}
__device__ __forceinline__ float rcpf(float v) {
    float r; asm("rcp.approx.f32 %0, %1;" : "=f"(r) : "f"(v)); return r;
}
__device__ __forceinline__ void cp16(uint32_t saddr, const void* gaddr) {
    asm volatile("cp.async.cg.shared.global [%0], [%1], 16;"
                 :: "r"(saddr), "l"(gaddr));
}
#define CP_COMMIT() asm volatile("cp.async.commit_group;")
#define CP_WAIT1()  asm volatile("cp.async.wait_group 1;")

// ---------------------------------------------------------------------------
// K1: g[b][t] = elu(cos_sim(latch_enable, x[b,t,:])). One warp per (b,t).
// ---------------------------------------------------------------------------
__global__ void __launch_bounds__(256) precompute_g_kernel(
    const float* __restrict__ x,
    const float* __restrict__ le)
{
    const int warp = threadIdx.x >> 5;
    const int lane = threadIdx.x & 31;
    const int bt   = blockIdx.x * 8 + warp;
    const float* xp = x + (size_t)bt * TD;

    float dot = 0.f, nx = 0.f, nl = 0.f;
#pragma unroll
    for (int k = 0; k < 8; k++) {
        float xv = xp[lane + k * 32];
        float lv = le[lane + k * 32];
        dot = fmaf(lv, xv, dot);
        nx  = fmaf(xv, xv, nx);
        nl  = fmaf(lv, lv, nl);
    }
#pragma unroll
    for (int o = 16; o; o >>= 1) {
        dot += __shfl_xor_sync(0xffffffffu, dot, o);
        nx  += __shfl_xor_sync(0xffffffffu, nx,  o);
        nl  += __shfl_xor_sync(0xffffffffu, nl,  o);
    }
    if (lane == 0) {
        float an = fmaxf(sqrtf(nl), 1e-8f);
        float bn = fmaxf(sqrtf(nx), 1e-8f);
        float c  = dot / (an * bn);
        g_scratch[bt] = (c > 0.f) ? c : expm1f(c);
    }
}

// ---------------------------------------------------------------------------
// K2ab: fused latch scan + pop reduction. One CTA per batch; thread d carries
// latch[d]. Per step: warp butterfly into a per-warp smem row (no in-loop
// barrier). One __syncthreads, then thread t finishes pop[b][t].
// ---------------------------------------------------------------------------
__global__ void __launch_bounds__(256) latch_pop_kernel(
    const float* __restrict__ x,
    const float* __restrict__ should_pop,
    const float* __restrict__ latch_init)
{
    __shared__ float2 part[8][TT];    // 16 KB
    __shared__ float  spn[8];

    const int b    = blockIdx.x;
    const int d    = threadIdx.x;
    const int warp = d >> 5;
    const int lane = d & 31;

    const float sp = should_pop[d];
    float lat      = latch_init[b * TD + d];

    {
        float r = sp * sp;
#pragma unroll
        for (int o = 16; o; o >>= 1) r += __shfl_xor_sync(0xffffffffu, r, o);
        if (lane == 0) spn[warp] = r;
    }
    __syncthreads();
    float sp2 = 0.f;
#pragma unroll
    for (int w = 0; w < 8; w++) sp2 += spn[w];
    const float inv_an = 1.0f / fmaxf(sqrtf(sp2), 1e-8f);

    const float* xb = x + (size_t)b * TT * TD + d;
    const float* gb = g_scratch + b * TT;

#pragma unroll 4
    for (int t = 0; t < TT; t++) {
        float q0 = sp * lat, q1 = lat * lat;
#pragma unroll
        for (int o = 16; o; o >>= 1) {
            q0 += __shfl_xor_sync(0xffffffffu, q0, o);
            q1 += __shfl_xor_sync(0xffffffffu, q1, o);
        }
        if (lane == 0) part[warp][t] = make_float2(q0, q1);

        float xv = __ldg(xb + (size_t)t * TD);
        float gg = __ldg(gb + t);
        lat = fmaf(gg, xv - lat, lat);
    }
    __syncthreads();

    {
        const int t = d;
        float dot = 0.f, nl = 0.f;
#pragma unroll
        for (int w = 0; w < 8; w++) {
            float2 p = part[w][t];
            dot += p.x; nl += p.y;
        }
        float bn   = fmaxf(sqrtf(nl), 1e-8f);
        float cosv = dot * inv_an / bn;
        pop_scratch[b * TT + t] = (cosv > 0.f) ? cosv : expm1f(cosv);
    }
}

// ---------------------------------------------------------------------------
// K2c: pointer scan. One warp per batch. Sigma butterfly interleaved with the
// roll/lg2 chain; ex2.approx sharpen; rcp.approx for the (off-chain) 1/sigma;
// coef store deferred one step.
// ---------------------------------------------------------------------------
__global__ void __launch_bounds__(32) pointer_scan_kernel(
    const float* __restrict__ sharpen_ptr)
{
    const int b    = blockIdx.x;
    const int lane = threadIdx.x;
    const unsigned FULL = 0xffffffffu;

    const float s5 = sharpen_ptr[0];

    float Q = (lane == 0) ? 1.0f : 1e-6f;   // raw initial pointer

    const float* pb = pop_scratch + b * TT;
    float4*      cb = coef_buf + (size_t)b * TT * NS;

    float popPrev = 0.f, aPrev = 0.f, ePrev = 0.f, cPrev = 0.f;

#pragma unroll 4
    for (int t = 0; t < TT; t++) {
        const float pop  = __ldg(pb + t);
        const float push = 1.0f - pop;

        float sig = Q;
        float Qp = __shfl_sync(FULL, Q, (lane + 31) & 31);  // p_push source
        sig += __shfl_xor_sync(FULL, sig, 1);
        float Qm = __shfl_sync(FULL, Q, (lane + 1) & 31);   // p_pop source
        sig += __shfl_xor_sync(FULL, sig, 2);
        float np = fmaf(push, Qp, pop * Qm);                // unnormalized new ptr
        sig += __shfl_xor_sync(FULL, sig, 4);
        float lnp = __log2f(np);
        sig += __shfl_xor_sync(FULL, sig, 8);
        sig += __shfl_xor_sync(FULL, sig, 16);

        float invs = rcpf(sig);          // off the Q-chain; 1-ulp approx
        float lgs  = __log2f(sig);

        if (t > 0) {
            float w = popPrev * Q * invs;
            cb[(t - 1) * NS + lane] = make_float4(aPrev, ePrev, cPrev, w);
        }

        float e = push * (Qp * invs);
        float f = pop  * (Q  * invs);
        float a = 1.0f - e - f;
        float c = 1e-6f * f;

        float Qn = (np > 0.f) ? ex2f(s5 * (lnp - lgs)) : 0.f;

        Q = Qn;
        popPrev = pop; aPrev = a; ePrev = e; cPrev = c;
    }

    {
        float sig = Q;
#pragma unroll
        for (int o = 16; o; o >>= 1) sig += __shfl_xor_sync(FULL, sig, o);
        float invs = rcpf(fmaxf(sig, 1e-8f));
        float w = popPrev * Q * invs;
        cb[(TT - 1) * NS + lane] = make_float4(aPrev, ePrev, cPrev, w);
    }
}

// ---------------------------------------------------------------------------
// K3: stack recurrence. 512 threads (16 warps = 4/SMSP for latency hiding).
// Thread (h, d): h = tid>>8 owns slot half h*16..h*16+15 of column d.
// Warps 0-7 are h=0, warps 8-15 are h=1 -> every warp's coef read is a
// uniform broadcast (conflict-free), scalar float4 format. Halves combine
// readout partials via smem once per 8-step chunk using the EXISTING chunk
// barriers (h=1 writes partials during compute; h=0 adds + stores after).
// ---------------------------------------------------------------------------
__global__ void __launch_bounds__(512) stack_kernel(
    const float* __restrict__ x,
    float* __restrict__ out)
{
    __shared__ float4 cbuf[2][8][NS];   // 8 KB: 2 chunks x 8 steps x 32 slots
    __shared__ float  psum[8][TD];      // 8 KB: h=1 readout partials

    const int tid = threadIdx.x;
    const int b   = blockIdx.x;
    const int h   = tid >> 8;           // slot half
    const int d   = tid & 255;          // column

    const float4* cb = coef_buf + (size_t)b * TT * NS;
    const float*  xb = x   + (size_t)b * TT * TD + d;
    float*        ob = out + (size_t)b * TT * TD + d;

    float st[16];
#pragma unroll
    for (int n = 0; n < 16; n++) st[n] = 1e-6f;

    // prologue: chunks 0 and 1 in flight (256 float4 each; threads 0..255)
    if (tid < 256) {
        uint32_t s0 = (uint32_t)__cvta_generic_to_shared(&cbuf[0][0][0]);
        cp16(s0 + tid * 16,        &cb[tid]);
        cp16(s0 + 4096 + tid * 16, &cb[256 + tid]);
    }
    CP_COMMIT();   // group: chunk0+chunk1 (single group; wait 0 below)
    asm volatile("cp.async.wait_group 0;");
    __syncthreads();

    for (int k = 0; k < TT / 8; k++) {
        // prefetch this chunk's 8 x values (independent loads, MLP=8)
        float xv[8];
#pragma unroll
        for (int s = 0; s < 8; s++)
            xv[s] = __ldg(xb + (size_t)(k * 8 + s) * TD);

        float own[8];
#pragma unroll
        for (int s = 0; s < 8; s++) {
            const float4* cf = &cbuf[k & 1][s][h * 16];
            float s0 = 0.f, s1 = 0.f, s2 = 0.f, s3 = 0.f;
#pragma unroll
            for (int n = 0; n < 16; n += 4) {
                float4 k0 = cf[n];
                float4 k1 = cf[n + 1];
                float4 k2 = cf[n + 2];
                float4 k3 = cf[n + 3];
                float v0 = fmaf(k0.x, st[n],     fmaf(k0.y, xv[s], k0.z));
                float v1 = fmaf(k1.x, st[n + 1], fmaf(k1.y, xv[s], k1.z));
                float v2 = fmaf(k2.x, st[n + 2], fmaf(k2.y, xv[s], k2.z));
                float v3 = fmaf(k3.x, st[n + 3], fmaf(k3.y, xv[s], k3.z));
                st[n]     = v0;
                st[n + 1] = v1;
                st[n + 2] = v2;
                st[n + 3] = v3;
                s0 = fmaf(v0, k0.w, s0);
                s1 = fmaf(v1, k1.w, s1);
                s2 = fmaf(v2, k2.w, s2);
                s3 = fmaf(v3, k3.w, s3);
            }
            float ps = (s0 + s1) + (s2 + s3);
            if (h) psum[s][d] = ps;     // h=1 partial to smem
            else   own[s] = ps;         // h=0 partial in regs
        }

        __syncthreads();               // cbuf reads AND psum writes done

        if (h == 0) {
            // combine + store (coalesced, 256 threads cover all d)
#pragma unroll
            for (int s = 0; s < 8; s++)
                ob[(size_t)(k * 8 + s) * TD] = own[s] + psum[s][d];
            // stage chunk k+2 into the slot we just finished reading
            if (k + 2 < TT / 8) {
                uint32_t sa = (uint32_t)__cvta_generic_to_shared(&cbuf[k & 1][0][0]);
                cp16(sa + tid * 16, &cb[(size_t)(k + 2) * 256 + tid]);
            }
        }
        CP_COMMIT();                   // uniform group count (empty for h=1)
        CP_WAIT1();                    // chunk k+1 complete (this thread)
        __syncthreads();               // ... and visible to all
    }
}

// ---------------------------------------------------------------------------
// metadata order: x[B*T*D], should_pop[D], sharpen_pointer[1],
//                 latch_enable[D], latch_init[B*D]  -> out[B*T*D] float32
// ---------------------------------------------------------------------------
extern "C" void kernel_launch(void* const* d_in, const int* in_sizes, int n_in,
                              void* d_out, int out_size)
{
    const float* x   = (const float*)d_in[0];
    const float* sp  = (const float*)d_in[1];
    const float* shp = (const float*)d_in[2];
    const float* le  = (const float*)d_in[3];
    const float* li  = (const float*)d_in[4];
    float* out = (float*)d_out;

    precompute_g_kernel<<<(BB * TT) / 8, 256>>>(x, le);
    latch_pop_kernel<<<BB, 256>>>(x, sp, li);
    pointer_scan_kernel<<<BB, 32>>>(shp);
    stack_kernel<<<BB, 512>>>(x, out);
}